// round 4
// baseline (speedup 1.0000x reference)
#include <cuda_runtime.h>

// DepthWiseConv1d: inputs [B=32, C=128, L=8192] fp32, weight [C,3], bias [C].
// out[b,c,l] = w0*x[l-1] + w1*x[l] + w2*x[l+1] + bias  (zero pad at l=-1, l=L)
//
// Pure HBM-streaming kernel: 1 float4 load + 2 scalar halo loads (L1-hit) +
// 1 float4 store per thread. Target: LTS/HBM ceiling (~41 us floor).

#define L_LEN 8192
#define C_CH  128
#define L_VEC (L_LEN / 4)   // 2048 float4 per row

__global__ __launch_bounds__(256) void dwconv1d_kernel(
    const float* __restrict__ x,
    const float* __restrict__ weight,   // [C, 3]
    const float* __restrict__ bias,     // [C]
    float* __restrict__ out,
    int total_vec)                      // B*C*L_VEC
{
    int idx = blockIdx.x * blockDim.x + threadIdx.x;
    if (idx >= total_vec) return;

    int lv  = idx & (L_VEC - 1);        // vec4 index within row
    int row = idx >> 11;                // idx / L_VEC  (L_VEC = 2048 = 2^11)
    int c   = row & (C_CH - 1);         // channel

    const float* xrow = x + (size_t)row * L_LEN;
    int l = lv << 2;                    // element index of first output

    // main vector load (coalesced 128b)
    float4 v = *reinterpret_cast<const float4*>(xrow + l);

    // halo loads: left neighbor of v.x, right neighbor of v.w (zero-padded)
    float left  = (l == 0)          ? 0.0f : __ldg(xrow + l - 1);
    float right = (l + 4 == L_LEN)  ? 0.0f : __ldg(xrow + l + 4);

    float w0 = __ldg(weight + 3 * c + 0);
    float w1 = __ldg(weight + 3 * c + 1);
    float w2 = __ldg(weight + 3 * c + 2);
    float b  = __ldg(bias + c);

    float4 o;
    o.x = fmaf(w0, left, fmaf(w1, v.x, fmaf(w2, v.y, b)));
    o.y = fmaf(w0, v.x,  fmaf(w1, v.y, fmaf(w2, v.z, b)));
    o.z = fmaf(w0, v.y,  fmaf(w1, v.z, fmaf(w2, v.w, b)));
    o.w = fmaf(w0, v.z,  fmaf(w1, v.w, fmaf(w2, right, b)));

    *reinterpret_cast<float4*>(out + (size_t)row * L_LEN + l) = o;
}

extern "C" void kernel_launch(void* const* d_in, const int* in_sizes, int n_in,
                              void* d_out, int out_size)
{
    const float* x      = (const float*)d_in[0];   // [32,128,8192]
    const float* weight = (const float*)d_in[1];   // [128,3]
    const float* bias   = (const float*)d_in[2];   // [128]
    float* out = (float*)d_out;

    int total_vec = out_size / 4;                  // 32*128*8192/4 = 8388608
    int threads = 256;
    int blocks = (total_vec + threads - 1) / threads;
    dwconv1d_kernel<<<blocks, threads>>>(x, weight, bias, out, total_vec);
}